// round 6
// baseline (speedup 1.0000x reference)
#include <cuda_runtime.h>
#include <cstdint>

#define N 8192
#define D 64
#define E 262144

// ---------------------------------------------------------------------------
// Scratch (__device__ globals; no allocations allowed)
// ---------------------------------------------------------------------------
__device__ float g_sk[N * D];     // normalized state_K
__device__ float g_g[N];          // tanh(state_H)
__device__ float g_zt[N];         // 0.5 * W_hop^T @ g accumulator
__device__ float g_om[D * D];     // antisymmetrized (omega - omega^T)/2

__device__ int g_cntK[N],  g_cntHK[N];          // per-node degree counters
__device__ int g_offK[N + 1], g_offHK[N + 1];   // CSR offsets
__device__ int g_curK[N],  g_curHK[N];          // fill cursors
__device__ int g_adjK[2 * E], g_adjHK[2 * E];   // adjacency (other endpoint)

__device__ __forceinline__ void red_add_v4(float* p, float4 v) {
    asm volatile("red.global.add.v4.f32 [%0], {%1,%2,%3,%4};"
                 :: "l"(p), "f"(v.x), "f"(v.y), "f"(v.z), "f"(v.w)
                 : "memory");
}

// ---------------------------------------------------------------------------
// prep: sk = normalize rows, g = tanh(H), zero zt + degree counters,
//       out_fH = -H, block 0 additionally builds antisymmetrized omega.
// grid 1024 x 256 : one warp per sk row.
// ---------------------------------------------------------------------------
__global__ void __launch_bounds__(256) prep_kernel(
    const float* __restrict__ stateH,
    const float* __restrict__ stateK,
    const float* __restrict__ omega,
    float* __restrict__ outH)
{
    int tid  = threadIdx.x;
    int gtid = blockIdx.x * 256 + tid;

    if (blockIdx.x == 0) {
        #pragma unroll
        for (int t = tid; t < D * D; t += 256) {
            int d = t >> 6, c = t & 63;
            g_om[t] = 0.5f * (omega[t] - omega[c * D + d]);
        }
    }

    int row  = gtid >> 5;           // 0..8191
    int lane = tid & 31;
    float2 v = ((const float2*)(stateK + (size_t)row * D))[lane];
    float ss = v.x * v.x + v.y * v.y;
    #pragma unroll
    for (int o = 16; o; o >>= 1) ss += __shfl_xor_sync(0xffffffffu, ss, o);
    float inv = rsqrtf(ss);
    ((float2*)(g_sk + (size_t)row * D))[lane] = make_float2(v.x * inv, v.y * inv);

    if (gtid < N) {
        float h = stateH[gtid];
        g_g[gtid]   = tanhf(h);
        g_zt[gtid]  = 0.f;
        g_cntK[gtid]  = 0;
        g_cntHK[gtid] = 0;
        outH[gtid] = -h;
    }
}

// ---------------------------------------------------------------------------
// count: per-node degrees for both edge lists. thread per edge pair.
// ---------------------------------------------------------------------------
__global__ void __launch_bounds__(256) count_kernel(
    const int* __restrict__ indK, const int* __restrict__ indHK)
{
    int e = blockIdx.x * 256 + threadIdx.x;   // [0, E)
    int a = indK[2 * e],  b = indK[2 * e + 1];
    atomicAdd(&g_cntK[a], 1);
    atomicAdd(&g_cntK[b], 1);
    int i = indHK[2 * e], j = indHK[2 * e + 1];
    atomicAdd(&g_cntHK[i], 1);
    atomicAdd(&g_cntHK[j], 1);
}

// ---------------------------------------------------------------------------
// scan: exclusive prefix over 8192 counts, per list (blockIdx = list).
// 1024 threads x 8 elems; Hillis-Steele over thread sums in shared.
// ---------------------------------------------------------------------------
__global__ void __launch_bounds__(1024) scan_kernel()
{
    __shared__ int sums[1024];
    int list = blockIdx.x;
    const int* cnt = list ? g_cntHK : g_cntK;
    int* off = list ? g_offHK : g_offK;
    int* cur = list ? g_curHK : g_curK;

    int t = threadIdx.x;
    int v[8];
    int s = 0;
    #pragma unroll
    for (int q = 0; q < 8; q++) { v[q] = cnt[t * 8 + q]; s += v[q]; }
    sums[t] = s;
    __syncthreads();
    #pragma unroll
    for (int d = 1; d < 1024; d <<= 1) {
        int x = (t >= d) ? sums[t - d] : 0;
        __syncthreads();
        sums[t] += x;
        __syncthreads();
    }
    int run = (t == 0) ? 0 : sums[t - 1];
    #pragma unroll
    for (int q = 0; q < 8; q++) {
        off[t * 8 + q] = run;
        cur[t * 8 + q] = run;
        run += v[q];
    }
    if (t == 1023) off[N] = run;    // = 2E
}

// ---------------------------------------------------------------------------
// fill: write adjacency entries (other endpoint) at atomically bumped cursors.
// ---------------------------------------------------------------------------
__global__ void __launch_bounds__(256) fill_kernel(
    const int* __restrict__ indK, const int* __restrict__ indHK)
{
    int e = blockIdx.x * 256 + threadIdx.x;
    int a = indK[2 * e],  b = indK[2 * e + 1];
    g_adjK[atomicAdd(&g_curK[a], 1)] = b;
    g_adjK[atomicAdd(&g_curK[b], 1)] = a;
    int i = indHK[2 * e], j = indHK[2 * e + 1];
    g_adjHK[atomicAdd(&g_curHK[i], 1)] = j;
    g_adjHK[atomicAdd(&g_curHK[j], 1)] = i;
}

// ---------------------------------------------------------------------------
// matvec: single pass over W_hop (256 MB) computing BOTH
//   y  = W_hop  @ g  (row dots)  -> f_H += 0.5*y (atomic)
//   yT = W_hop^T @ g (col partials) -> g_zt += 0.5*yT (red.v4)
// grid 512 x 256, 16 rows/block, g in shared.
// ---------------------------------------------------------------------------
__global__ void __launch_bounds__(256) matvec_kernel(
    const float* __restrict__ W,
    float* __restrict__ outH)
{
    __shared__ float4 gsh[N / 4];
    int tid = threadIdx.x;
    #pragma unroll
    for (int k = 0; k < 8; k++)
        gsh[tid + 256 * k] = ((const float4*)g_g)[tid + 256 * k];
    __syncthreads();
    const float* gs = (const float*)gsh;

    float4 va[8];
    #pragma unroll
    for (int k = 0; k < 8; k++) va[k] = make_float4(0.f, 0.f, 0.f, 0.f);

    int r0 = blockIdx.x * 16;
    for (int r = 0; r < 16; r++) {
        const float4* rowp = (const float4*)(W + (size_t)(r0 + r) * N);
        float gr = gs[r0 + r];
        float dp = 0.f;
        #pragma unroll
        for (int k = 0; k < 8; k++) {
            float4 w  = __ldcs(&rowp[tid + 256 * k]);
            float4 gv = gsh[tid + 256 * k];
            dp = fmaf(w.x, gv.x, dp); dp = fmaf(w.y, gv.y, dp);
            dp = fmaf(w.z, gv.z, dp); dp = fmaf(w.w, gv.w, dp);
            va[k].x = fmaf(w.x, gr, va[k].x);
            va[k].y = fmaf(w.y, gr, va[k].y);
            va[k].z = fmaf(w.z, gr, va[k].z);
            va[k].w = fmaf(w.w, gr, va[k].w);
        }
        #pragma unroll
        for (int o = 16; o; o >>= 1) dp += __shfl_xor_sync(0xffffffffu, dp, o);
        if ((tid & 31) == 0) atomicAdd(&outH[r0 + r], 0.5f * dp);
    }
    #pragma unroll
    for (int k = 0; k < 8; k++) {
        int i4 = tid + 256 * k;
        red_add_v4(g_zt + 4 * i4,
                   make_float4(0.5f * va[k].x, 0.5f * va[k].y,
                               0.5f * va[k].z, 0.5f * va[k].w));
    }
}

// ---------------------------------------------------------------------------
// gather: warp per node. Pure gathers, zero scatter atomics.
//   K  edges:  acc += poly(<sk_n,sk_j>) * sk_j
//   HK edges:  Gram=<sk_n,sk_j>, wij = sym W; hk += Gram*wij*g_j;
//              acc += (-g_n*g_j*wij/kK) * sk_j
//   f_H[n] += zt[n] + hk/kH;  f_K row = -acc + sk*<sk,acc> + sk @ Om.
// Edge batches of 4 for MLP; Om staged per block from precomputed g_om.
// grid 1024 x 256 (8 warps = 8 nodes per block).
// ---------------------------------------------------------------------------
__global__ void __launch_bounds__(256) gather_kernel(
    const float* __restrict__ W,
    const float* __restrict__ coeffs,
    const float* __restrict__ kKp,
    const float* __restrict__ kHp,
    float* __restrict__ out)
{
    __shared__ float Om[D * D];
    int tid = threadIdx.x;
    #pragma unroll
    for (int t = tid; t < D * D; t += 256) Om[t] = g_om[t];
    __syncthreads();

    int n    = blockIdx.x * 8 + (tid >> 5);
    int lane = tid & 31;

    float2 skn = ((const float2*)(g_sk + (size_t)n * D))[lane];
    float  gn  = g_g[n];
    float c0 = coeffs[0], c1 = coeffs[1], c2 = coeffs[2], c3 = coeffs[3];
    float ikK = 1.f / *kKp, ikH = 1.f / *kHp;

    float2 acc = make_float2(0.f, 0.f);

    // ---------------- K list ----------------
    {
        int s = g_offK[n], e = g_offK[n + 1];
        for (int b = s; b < e; b += 4) {
            int m = e - b;
            float2 skj[4]; float pd[4];
            #pragma unroll
            for (int q = 0; q < 4; q++) {
                int ee = (q < m) ? (b + q) : b;
                int j  = g_adjK[ee];
                skj[q] = ((const float2*)(g_sk + (size_t)j * D))[lane];
                pd[q]  = skn.x * skj[q].x + skn.y * skj[q].y;
            }
            #pragma unroll
            for (int o = 16; o; o >>= 1) {
                #pragma unroll
                for (int q = 0; q < 4; q++)
                    pd[q] += __shfl_xor_sync(0xffffffffu, pd[q], o);
            }
            #pragma unroll
            for (int q = 0; q < 4; q++) {
                float sd = pd[q];
                float coef = sd * (c0 + sd * (c1 + sd * (c2 + sd * c3)));
                if (q < m) {
                    acc.x = fmaf(coef, skj[q].x, acc.x);
                    acc.y = fmaf(coef, skj[q].y, acc.y);
                }
            }
        }
    }

    // ---------------- HK list ----------------
    float hk = 0.f;
    {
        int s = g_offHK[n], e = g_offHK[n + 1];
        for (int b = s; b < e; b += 4) {
            int m = e - b;
            float2 skj[4]; float pd[4]; float gj[4], wij[4];
            #pragma unroll
            for (int q = 0; q < 4; q++) {
                int ee = (q < m) ? (b + q) : b;
                int j  = g_adjHK[ee];
                skj[q] = ((const float2*)(g_sk + (size_t)j * D))[lane];
                pd[q]  = skn.x * skj[q].x + skn.y * skj[q].y;
                gj[q]  = g_g[j];
                wij[q] = 0.5f * (__ldg(&W[(size_t)n * N + j]) +
                                 __ldg(&W[(size_t)j * N + n]));
            }
            #pragma unroll
            for (int o = 16; o; o >>= 1) {
                #pragma unroll
                for (int q = 0; q < 4; q++)
                    pd[q] += __shfl_xor_sync(0xffffffffu, pd[q], o);
            }
            #pragma unroll
            for (int q = 0; q < 4; q++) {
                if (q < m) {
                    hk = fmaf(pd[q] * wij[q], gj[q], hk);
                    float coef = -gn * gj[q] * wij[q] * ikK;
                    acc.x = fmaf(coef, skj[q].x, acc.x);
                    acc.y = fmaf(coef, skj[q].y, acc.y);
                }
            }
        }
    }

    // ---------------- f_H finish ----------------
    if (lane == 0) out[n] += g_zt[n] + hk * ikH;

    // ---------------- projection + omega rotation ----------------
    float dp = skn.x * acc.x + skn.y * acc.y;
    #pragma unroll
    for (int o = 16; o; o >>= 1) dp += __shfl_xor_sync(0xffffffffu, dp, o);

    const float2* Om2 = (const float2*)Om;
    float ax = 0.f, ay = 0.f;
    #pragma unroll
    for (int d = 0; d < D; d++) {
        float sv = __shfl_sync(0xffffffffu, (d & 1) ? skn.y : skn.x, d >> 1);
        float2 o = Om2[d * 32 + lane];
        ax = fmaf(sv, o.x, ax);
        ay = fmaf(sv, o.y, ay);
    }

    float2 o2;
    o2.x = -acc.x + skn.x * dp + ax;
    o2.y = -acc.y + skn.y * dp + ay;
    ((float2*)(out + N))[n * 32 + lane] = o2;
}

// ---------------------------------------------------------------------------
extern "C" void kernel_launch(void* const* d_in, const int* in_sizes, int n_in,
                              void* d_out, int out_size)
{
    const float* stateH = (const float*)d_in[0];
    const float* stateK = (const float*)d_in[1];
    const float* W      = (const float*)d_in[2];
    const float* coeffs = (const float*)d_in[3];
    const float* omega  = (const float*)d_in[4];
    const int*   indK   = (const int*)  d_in[5];
    const int*   indHK  = (const int*)  d_in[6];
    const float* kK     = (const float*)d_in[7];
    const float* kH     = (const float*)d_in[8];
    float* out = (float*)d_out;

    prep_kernel  <<<1024, 256>>>(stateH, stateK, omega, out);
    count_kernel <<<1024, 256>>>(indK, indHK);
    scan_kernel  <<<2, 1024>>>();
    fill_kernel  <<<1024, 256>>>(indK, indHK);
    matvec_kernel<<<512,  256>>>(W, out);
    gather_kernel<<<1024, 256>>>(W, coeffs, kK, kH, out);
}

// round 7
// speedup vs baseline: 1.4636x; 1.4636x over previous
#include <cuda_runtime.h>
#include <cuda_fp16.h>
#include <cstdint>

#define N 8192
#define D 64
#define E 262144

// Scratch (no allocations allowed — __device__ globals)
__device__ float  g_sk[N * D];    // normalized state_K (fp32)
__device__ __half g_skh[N * D];   // normalized state_K (fp16, for edge gathers)
__device__ float  g_g[N];         // tanh(state_H)
__device__ float  g_fk[N * D];    // f_K accumulator (pre-projection)
__device__ float  g_zt[N];        // 0.5 * W_hop^T @ g accumulator

__device__ __forceinline__ void red_add_v4(float* p, float4 v) {
    asm volatile("red.global.add.v4.f32 [%0], {%1,%2,%3,%4};"
                 :: "l"(p), "f"(v.x), "f"(v.y), "f"(v.z), "f"(v.w)
                 : "memory");
}

// ---------------------------------------------------------------------------
// prep: sk = normalize(state_K rows) in fp32 AND fp16, g = tanh(state_H),
//       zero accumulators, out_fH = -state_H.
// grid 1024 x 256 : one warp per row of state_K.
// ---------------------------------------------------------------------------
__global__ void __launch_bounds__(256) prep_kernel(
    const float* __restrict__ stateH,
    const float* __restrict__ stateK,
    float* __restrict__ outH)
{
    int tid  = threadIdx.x;
    int gtid = blockIdx.x * 256 + tid;

    // zero f_K accumulator: 524288 floats = 262144 float2 = exactly grid size
    ((float2*)g_fk)[gtid] = make_float2(0.f, 0.f);

    int row  = gtid >> 5;           // 0..8191
    int lane = tid & 31;
    float2 v = ((const float2*)(stateK + (size_t)row * D))[lane];
    float ss = v.x * v.x + v.y * v.y;
    #pragma unroll
    for (int o = 16; o; o >>= 1) ss += __shfl_xor_sync(0xffffffffu, ss, o);
    float inv = rsqrtf(ss);
    float2 s2 = make_float2(v.x * inv, v.y * inv);
    ((float2*)(g_sk + (size_t)row * D))[lane] = s2;
    ((__half2*)(g_skh + (size_t)row * D))[lane] = __float22half2_rn(s2);

    if (gtid < N) {
        float h = stateH[gtid];
        g_g[gtid]  = tanhf(h);
        g_zt[gtid] = 0.f;
        outH[gtid] = -h;
    }
}

// ---------------------------------------------------------------------------
// matvec: single pass over W_hop (256 MB) computing BOTH
//   y  = W_hop  @ g  (row dot products, block owns 16 full rows)
//   yT = W_hop^T @ g (column partials in registers, flushed via red.v4)
// f_H += 0.5*y (atomic per warp-partial), g_zt += 0.5*yT.
// grid 512 x 256, 16 rows/block, g cached in shared (32 KB).
// ---------------------------------------------------------------------------
__global__ void __launch_bounds__(256) matvec_kernel(
    const float* __restrict__ W,
    float* __restrict__ outH)
{
    __shared__ float4 gsh[N / 4];
    int tid = threadIdx.x;
    #pragma unroll
    for (int k = 0; k < 8; k++)
        gsh[tid + 256 * k] = ((const float4*)g_g)[tid + 256 * k];
    __syncthreads();
    const float* gs = (const float*)gsh;

    float4 va[8];
    #pragma unroll
    for (int k = 0; k < 8; k++) va[k] = make_float4(0.f, 0.f, 0.f, 0.f);

    int r0 = blockIdx.x * 16;
    for (int r = 0; r < 16; r++) {
        const float4* rowp = (const float4*)(W + (size_t)(r0 + r) * N);
        float gr = gs[r0 + r];
        float dp = 0.f;
        #pragma unroll
        for (int k = 0; k < 8; k++) {
            float4 w  = __ldcs(&rowp[tid + 256 * k]);   // streaming, evict-first
            float4 gv = gsh[tid + 256 * k];
            dp = fmaf(w.x, gv.x, dp); dp = fmaf(w.y, gv.y, dp);
            dp = fmaf(w.z, gv.z, dp); dp = fmaf(w.w, gv.w, dp);
            va[k].x = fmaf(w.x, gr, va[k].x);
            va[k].y = fmaf(w.y, gr, va[k].y);
            va[k].z = fmaf(w.z, gr, va[k].z);
            va[k].w = fmaf(w.w, gr, va[k].w);
        }
        #pragma unroll
        for (int o = 16; o; o >>= 1) dp += __shfl_xor_sync(0xffffffffu, dp, o);
        if ((tid & 31) == 0) atomicAdd(&outH[r0 + r], 0.5f * dp);
    }
    #pragma unroll
    for (int k = 0; k < 8; k++) {
        int i4 = tid + 256 * k;
        red_add_v4(g_zt + 4 * i4,
                   make_float4(0.5f * va[k].x, 0.5f * va[k].y,
                               0.5f * va[k].z, 0.5f * va[k].w));
    }
}

// ---------------------------------------------------------------------------
// edges: both lists fused. Half-warp (16 lanes) per edge.
// sk rows gathered as fp16 (128B/row, HALF the gather bytes), converted to
// fp32 in registers; all math and the red.v4 scatter remain fp32.
// grid 32768 x 256 (16 edges per block).
// ---------------------------------------------------------------------------
__global__ void __launch_bounds__(256) edge_kernel(
    const int* __restrict__ indK,
    const int* __restrict__ indHK,
    const float* __restrict__ W,
    const float* __restrict__ coeffs,
    const float* __restrict__ kKp,
    const float* __restrict__ kHp,
    float* __restrict__ outH)
{
    int gtid = blockIdx.x * 256 + threadIdx.x;
    int edge = gtid >> 4;               // half-warp id = edge id, [0, 2E)
    int l    = threadIdx.x & 15;

    bool isK = edge < E;
    int e2   = isK ? edge : edge - E;
    const int* ind = isK ? indK : indHK;
    int i = ind[2 * e2];
    int j = ind[2 * e2 + 1];

    // fp16 gather: 4 halves (8B) per lane = 128B per row per half-warp
    uint2 hi2 = ((const uint2*)(g_skh + (size_t)i * D))[l];
    uint2 hj2 = ((const uint2*)(g_skh + (size_t)j * D))[l];
    float2 a0 = __half22float2(*(const __half2*)&hi2.x);
    float2 a1 = __half22float2(*(const __half2*)&hi2.y);
    float2 b0 = __half22float2(*(const __half2*)&hj2.x);
    float2 b1 = __half22float2(*(const __half2*)&hj2.y);
    float4 si = make_float4(a0.x, a0.y, a1.x, a1.y);
    float4 sj = make_float4(b0.x, b0.y, b1.x, b1.y);

    float dp = si.x * sj.x + si.y * sj.y + si.z * sj.z + si.w * sj.w;
    #pragma unroll
    for (int o = 8; o; o >>= 1) dp += __shfl_xor_sync(0xffffffffu, dp, o, 16);

    float coef;
    if (isK) {
        float c0 = coeffs[0], c1 = coeffs[1], c2 = coeffs[2], c3 = coeffs[3];
        coef = dp * (c0 + dp * (c1 + dp * (c2 + dp * c3)));
    } else {
        float wij = 0.5f * (W[(size_t)i * N + j] + W[(size_t)j * N + i]);
        float gi = g_g[i], gj = g_g[j];
        if (l == 0) {
            float ikH = 1.f / *kHp;
            atomicAdd(&outH[i], dp * wij * gj * ikH);
            atomicAdd(&outH[j], dp * wij * gi * ikH);
        }
        coef = -gi * gj * wij / *kKp;
    }

    red_add_v4(g_fk + (size_t)i * D + 4 * l,
               make_float4(coef * sj.x, coef * sj.y, coef * sj.z, coef * sj.w));
    red_add_v4(g_fk + (size_t)j * D + 4 * l,
               make_float4(coef * si.x, coef * si.y, coef * si.z, coef * si.w));
}

// ---------------------------------------------------------------------------
// final: f_H += zT;  f_K = -raw + sk * <sk, raw> + sk @ (omega - omega^T)/2.
// grid 512 x 256; each warp handles 2 rows (block = 16 rows).
// ---------------------------------------------------------------------------
#define FB 512                      // final grid
#define RPW 2                       // rows per warp

__global__ void __launch_bounds__(256, 1) final_kernel(
    const float* __restrict__ omega,
    float* __restrict__ out)
{
    __shared__ float Om[D * D];          // antisymmetrized, row-major Om[d][c]
    int tid  = threadIdx.x;
    int w    = tid >> 5;
    int lane = tid & 31;
    int rbase = blockIdx.x * (8 * RPW) + w * RPW;

    // ---- prefetch the per-row global data before touching shared ----
    float2 raw[RPW], skr[RPW];
    #pragma unroll
    for (int rr = 0; rr < RPW; rr++) {
        raw[rr] = ((const float2*)(g_fk + (size_t)(rbase + rr) * D))[lane];
        skr[rr] = ((const float2*)(g_sk + (size_t)(rbase + rr) * D))[lane];
    }
    // f_H += zT : 8192 / 512 blocks = 16 elems per block
    if (tid < N / FB) {
        int hidx = blockIdx.x * (N / FB) + tid;
        out[hidx] += g_zt[hidx];
    }

    // ---- stage antisymmetrized Omega (runs while prefetches are in flight) --
    #pragma unroll
    for (int t = tid; t < D * D; t += 256) {
        int d = t >> 6, c = t & 63;
        Om[t] = 0.5f * (omega[t] - omega[c * D + d]);
    }
    __syncthreads();

    // ---- dp[rr] = <sk_r, raw_r> (independent shfl trees, interleaved) ----
    float dp[RPW];
    #pragma unroll
    for (int rr = 0; rr < RPW; rr++)
        dp[rr] = skr[rr].x * raw[rr].x + skr[rr].y * raw[rr].y;
    #pragma unroll
    for (int o = 16; o; o >>= 1) {
        #pragma unroll
        for (int rr = 0; rr < RPW; rr++)
            dp[rr] += __shfl_xor_sync(0xffffffffu, dp[rr], o);
    }

    // ---- acc[rr][c] = sum_d sk[r][d] * Om[d][c]; lane owns cols {2l,2l+1}.
    const float2* Om2 = (const float2*)Om;
    float ax[RPW], ay[RPW];
    #pragma unroll
    for (int rr = 0; rr < RPW; rr++) { ax[rr] = 0.f; ay[rr] = 0.f; }
    #pragma unroll
    for (int d = 0; d < D; d++) {
        float2 o = Om2[d * 32 + lane];          // contiguous, conflict-free
        #pragma unroll
        for (int rr = 0; rr < RPW; rr++) {
            float s = __shfl_sync(0xffffffffu,
                                  (d & 1) ? skr[rr].y : skr[rr].x, d >> 1);
            ax[rr] = fmaf(s, o.x, ax[rr]);
            ay[rr] = fmaf(s, o.y, ay[rr]);
        }
    }

    #pragma unroll
    for (int rr = 0; rr < RPW; rr++) {
        float2 o2;
        o2.x = -raw[rr].x + skr[rr].x * dp[rr] + ax[rr];
        o2.y = -raw[rr].y + skr[rr].y * dp[rr] + ay[rr];
        ((float2*)(out + N))[(rbase + rr) * 32 + lane] = o2;
    }
}

// ---------------------------------------------------------------------------
extern "C" void kernel_launch(void* const* d_in, const int* in_sizes, int n_in,
                              void* d_out, int out_size)
{
    const float* stateH = (const float*)d_in[0];
    const float* stateK = (const float*)d_in[1];
    const float* W      = (const float*)d_in[2];
    const float* coeffs = (const float*)d_in[3];
    const float* omega  = (const float*)d_in[4];
    const int*   indK   = (const int*)  d_in[5];
    const int*   indHK  = (const int*)  d_in[6];
    const float* kK     = (const float*)d_in[7];
    const float* kH     = (const float*)d_in[8];
    float* out = (float*)d_out;

    prep_kernel  <<<1024, 256>>>(stateH, stateK, out);
    matvec_kernel<<<512,  256>>>(W, out);
    edge_kernel  <<<32768, 256>>>(indK, indHK, W, coeffs, kK, kH, out);
    final_kernel <<<FB, 256>>>(omega, out);
}